// round 15
// baseline (speedup 1.0000x reference)
#include <cuda_runtime.h>
#include <cuda_fp16.h>
#include <math.h>
#include <stdint.h>

#define D_MODEL 1024
#define SEQ     2048
#define BATCH   2
#define NTOK    4096
#define NHEAD   16
#define HD      64

// ---------------- scratch ----------------
__device__ float  g_x1  [NTOK * D_MODEL];
__device__ __half g_qkv [NTOK * 3 * D_MODEL];
__device__ __half g_ln1h[NTOK * D_MODEL];
__device__ __half g_attnh[NTOK * D_MODEL];
__device__ __half g_ln2h[NTOK * D_MODEL];
__device__ __half g_hh  [NTOK * 4 * D_MODEL];
// fp16 weights, k-pair interleaved: w16[((k>>1)*N + n)*2 + (k&1)]
__device__ __half g_wattn [D_MODEL * 3 * D_MODEL];
__device__ __half g_wproj [D_MODEL * D_MODEL];
__device__ __half g_wfc   [D_MODEL * 4 * D_MODEL];
__device__ __half g_wproj2[4 * D_MODEL * D_MODEL];

// ---------------- weight fp32 -> fp16 interleaved (vectorized) ----------------
__global__ __launch_bounds__(256) void wconv(const float* __restrict__ w,
                                             __half* __restrict__ o,
                                             int K, int N)
{
    int idx = blockIdx.x * 256 + threadIdx.x;   // over (K/2)*(N/4)
    int nq4 = N >> 2;
    if (idx >= (K / 2) * nq4) return;
    int kp = idx / nq4, n = (idx - kp * nq4) * 4;
    float4 lo = *(const float4*)(w + (size_t)(2 * kp) * N + n);
    float4 hi = *(const float4*)(w + (size_t)(2 * kp + 1) * N + n);
    __half2 h0 = __floats2half2_rn(lo.x, hi.x);
    __half2 h1 = __floats2half2_rn(lo.y, hi.y);
    __half2 h2 = __floats2half2_rn(lo.z, hi.z);
    __half2 h3 = __floats2half2_rn(lo.w, hi.w);
    uint4 pack;
    pack.x = *(uint32_t*)&h0; pack.y = *(uint32_t*)&h1;
    pack.z = *(uint32_t*)&h2; pack.w = *(uint32_t*)&h3;
    *(uint4*)(o + ((size_t)kp * N + n) * 2) = pack;
}

// ---------------- LayerNorm -> fp16 ----------------
__global__ __launch_bounds__(256) void ln_kernel(const float* __restrict__ x,
                                                 const float* __restrict__ w,
                                                 const float* __restrict__ b,
                                                 __half* __restrict__ y)
{
    int row = blockIdx.x;
    int tid = threadIdx.x;
    const float4* xr = (const float4*)(x + (size_t)row * D_MODEL);
    float4 v = xr[tid];

    __shared__ float red[8];

    float s = v.x + v.y + v.z + v.w;
    #pragma unroll
    for (int o = 16; o > 0; o >>= 1) s += __shfl_xor_sync(0xffffffffu, s, o);
    if ((tid & 31) == 0) red[tid >> 5] = s;
    __syncthreads();
    float tot = red[0] + red[1] + red[2] + red[3] + red[4] + red[5] + red[6] + red[7];
    float mean = tot * (1.0f / 1024.0f);

    float a0 = v.x - mean, a1 = v.y - mean, a2 = v.z - mean, a3 = v.w - mean;
    __syncthreads();
    float q = a0*a0 + a1*a1 + a2*a2 + a3*a3;
    #pragma unroll
    for (int o = 16; o > 0; o >>= 1) q += __shfl_xor_sync(0xffffffffu, q, o);
    if ((tid & 31) == 0) red[tid >> 5] = q;
    __syncthreads();
    float ssq = red[0] + red[1] + red[2] + red[3] + red[4] + red[5] + red[6] + red[7];

    float sd  = sqrtf(ssq * (1.0f / 1023.0f));
    float inv = 1.0f / (sd + 1e-5f);

    float4 wv = ((const float4*)w)[tid];
    float4 bv = ((const float4*)b)[tid];
    __half2* yr = (__half2*)(y + (size_t)row * D_MODEL);
    yr[2 * tid]     = __floats2half2_rn(wv.x * (a0 * inv) + bv.x,
                                        wv.y * (a1 * inv) + bv.y);
    yr[2 * tid + 1] = __floats2half2_rn(wv.z * (a2 * inv) + bv.z,
                                        wv.w * (a3 * inv) + bv.w);
}

__device__ __forceinline__ float gelu_f(float x)
{
    float x3 = x * x * x;
    return 0.5f * x * (1.0f + tanhf(0.7978845608028654f * (x + 0.044715f * x3)));
}

__device__ __forceinline__ void cp16(uint32_t dst, const void* src)
{
    asm volatile("cp.async.cg.shared.global [%0], [%1], 16;\n" :: "r"(dst), "l"(src));
}

#define MMA_F16(c, a, b) \
    asm volatile( \
        "mma.sync.aligned.m16n8k16.row.col.f32.f16.f16.f32 " \
        "{%0,%1,%2,%3}, {%4,%5,%6,%7}, {%8,%9}, {%0,%1,%2,%3};\n" \
        : "+f"((c)[0]), "+f"((c)[1]), "+f"((c)[2]), "+f"((c)[3]) \
        : "r"((a)[0]), "r"((a)[1]), "r"((a)[2]), "r"((a)[3]), \
          "r"((b)[0]), "r"((b)[1]))

#define LDSM_X4(r0, r1, r2, r3, addr) \
    asm volatile("ldmatrix.sync.aligned.m8n8.x4.shared.b16 {%0,%1,%2,%3}, [%4];" \
        : "=r"(r0), "=r"(r1), "=r"(r2), "=r"(r3) : "r"(addr))

// ---------------- fp16 GEMM 256x128x32, 512 threads, 3-stage cp.async ----------------
// 16 warps as 4(m) x 4(n); warp tile 64x32 (identical inner loop to the 620us best).
#define BM 256
#define BN 128
#define BKT 32
#define A_ROW_H 40
#define A_STAGE_BYTES (BM * A_ROW_H * 2)               // 20480
#define B_ROW_W 136
#define B_STAGE_BYTES (16 * B_ROW_W * 4)               // 8704
#define STAGE_BYTES (A_STAGE_BYTES + B_STAGE_BYTES)    // 29184
#define GEMM_SMEM_BYTES (3 * STAGE_BYTES)              // 87552

// MODE 0: Ch = A@B + bias (fp16) ; MODE 1: C = res + A@B + bias (fp32)
// MODE 2: Ch = gelu(A@B + bias) (fp16)
template<int MODE>
__global__ __launch_bounds__(512, 1) void gemm_fp16(const __half* __restrict__ A,
                                                    const __half* __restrict__ Bw16,
                                                    const float* __restrict__ bias,
                                                    const float* __restrict__ res,
                                                    float* __restrict__ C,
                                                    __half* __restrict__ Ch,
                                                    int M, int N, int K)
{
    extern __shared__ char smc[];
    int tid  = threadIdx.x;
    int bx = blockIdx.x, by = blockIdx.y;
    int warp = tid >> 5, lane = tid & 31;
    int wm = warp >> 2, wn = warp & 3;          // 4 x 4 warps, 64x32 warp tile
    int g = lane >> 2, tig = lane & 3;

    int lr8  = lane & 7;
    int aoff = ((lane & 8) ? 8 : 0);
    int koff = ((lane & 16) ? 8 : 0);

    const __half* Ablk = A + (size_t)(by * BM) * K;
    const __half* Bblk = Bw16 + (size_t)(bx * BN) * 2;

    float c[4][4][4];
    #pragma unroll
    for (int mt = 0; mt < 4; mt++)
        #pragma unroll
        for (int nt = 0; nt < 4; nt++)
            #pragma unroll
            for (int r = 0; r < 4; r++) c[mt][nt][r] = 0.0f;

    const int iters = K / BKT;
    uint32_t smem_base = (uint32_t)__cvta_generic_to_shared(smc);

    auto load_stage = [&](int it, int buf) {
        uint32_t as = smem_base + (uint32_t)(buf * STAGE_BYTES);
        uint32_t bs = as + A_STAGE_BYTES;
        int k0 = it * BKT;
        // A: 256 rows x 32 halfs = 1024 x 16B chunks (2/thread at 512 threads)
        #pragma unroll
        for (int i = 0; i < 2; i++) {
            int q = tid + 512 * i;
            int ar = q >> 2, ac = (q & 3) * 8;
            cp16(as + (uint32_t)(ar * (A_ROW_H * 2) + ac * 2),
                 Ablk + (size_t)ar * K + k0 + ac);
        }
        // B: 16 kpair rows x 128 words = 512 x 16B chunks (1/thread)
        {
            int br = tid >> 5, bc = (tid & 31) * 4;
            cp16(bs + (uint32_t)(br * (B_ROW_W * 4) + bc * 4),
                 Bblk + ((size_t)(k0 / 2 + br) * N + bc) * 2);
        }
        asm volatile("cp.async.commit_group;\n" ::: "memory");
    };

    load_stage(0, 0);
    if (iters > 1) load_stage(1, 1);

    for (int it = 0; it < iters; it++) {
        if (it + 1 < iters) asm volatile("cp.async.wait_group 1;\n" ::: "memory");
        else                asm volatile("cp.async.wait_group 0;\n" ::: "memory");
        __syncthreads();
        if (it + 2 < iters) load_stage(it + 2, (it + 2) % 3);

        const char* stg = smc + (it % 3) * STAGE_BYTES;
        const __half*  As = (const __half*)stg;
        const uint32_t* Bs = (const uint32_t*)(stg + A_STAGE_BYTES);

        #pragma unroll
        for (int s = 0; s < 2; s++) {
            uint32_t a[4][4], b[4][2];
            #pragma unroll
            for (int mt = 0; mt < 4; mt++) {
                const __half* p = As + (size_t)(wm * 64 + mt * 16 + lr8 + aoff) * A_ROW_H
                                     + s * 16 + koff;
                uint32_t ad = (uint32_t)__cvta_generic_to_shared(p);
                LDSM_X4(a[mt][0], a[mt][1], a[mt][2], a[mt][3], ad);
            }
            #pragma unroll
            for (int nt = 0; nt < 4; nt++) {
                int n = wn * 32 + nt * 8 + g;
                b[nt][0] = Bs[(s * 8 + tig) * B_ROW_W + n];
                b[nt][1] = Bs[(s * 8 + 4 + tig) * B_ROW_W + n];
            }
            #pragma unroll
            for (int mt = 0; mt < 4; mt++)
                #pragma unroll
                for (int nt = 0; nt < 4; nt++)
                    MMA_F16(c[mt][nt], a[mt], b[nt]);
        }
    }

    #pragma unroll
    for (int mt = 0; mt < 4; mt++) {
        int row0 = by * BM + wm * 64 + mt * 16 + g;
        #pragma unroll
        for (int nt = 0; nt < 4; nt++) {
            int col = bx * BN + wn * 32 + nt * 8 + tig * 2;
            float b0 = __ldg(bias + col), b1 = __ldg(bias + col + 1);
            float v0 = c[mt][nt][0] + b0, v1 = c[mt][nt][1] + b1;
            float v2 = c[mt][nt][2] + b0, v3 = c[mt][nt][3] + b1;
            if (MODE == 0) {
                *(__half2*)(Ch + (size_t)row0 * N + col) = __floats2half2_rn(v0, v1);
                *(__half2*)(Ch + (size_t)(row0 + 8) * N + col) = __floats2half2_rn(v2, v3);
            }
            if (MODE == 1) {
                const float* r0 = res + (size_t)row0 * N + col;
                const float* r1 = res + (size_t)(row0 + 8) * N + col;
                *(float2*)(C + (size_t)row0 * N + col) =
                    make_float2(v0 + r0[0], v1 + r0[1]);
                *(float2*)(C + (size_t)(row0 + 8) * N + col) =
                    make_float2(v2 + r1[0], v3 + r1[1]);
            }
            if (MODE == 2) {
                *(__half2*)(Ch + (size_t)row0 * N + col) =
                    __floats2half2_rn(gelu_f(v0), gelu_f(v1));
                *(__half2*)(Ch + (size_t)(row0 + 8) * N + col) =
                    __floats2half2_rn(gelu_f(v2), gelu_f(v3));
            }
        }
    }
}

// ---------------- fp16 flash attention (R13 exact: V-hoist, single K buffer) ----------------
#define QT 128
#define KT 64
#define TS_H 72
#define ATTN_SMEM ((QT*TS_H + KT*TS_H + KT*TS_H + QT*TS_H) * 2)

__global__ __launch_bounds__(256, 2) void attn_tc(const __half* __restrict__ qkv,
                                                  __half* __restrict__ out)
{
    extern __shared__ __half smh[];
    __half* Qs = smh;                       // [128][72]
    __half* Ks = Qs + QT * TS_H;            // [64][72]
    __half* Vt = Ks + KT * TS_H;            // [64 d][72 keys]
    __half* Ps = Vt + KT * TS_H;            // [128][72]

    int tid = threadIdx.x, warp = tid >> 5, lane = tid & 31;
    int g = lane >> 2, tig = lane & 3;
    int qb = gridDim.x - 1 - blockIdx.x;
    int h = blockIdx.y, b = blockIdx.z;

    const __half* base = qkv + (size_t)b * SEQ * (3 * D_MODEL) + h * HD;

    uint32_t qs_u = (uint32_t)__cvta_generic_to_shared(Qs);
    uint32_t ks_u = (uint32_t)__cvta_generic_to_shared(Ks);
    uint32_t* Vtw = (uint32_t*)Vt;
    const uint32_t* Qsw = (const uint32_t*)Qs;
    const uint32_t* Ksw = (const uint32_t*)Ks;
    const uint32_t* Vw  = (const uint32_t*)Vt;
    uint32_t* Psw = (uint32_t*)Ps;

    #pragma unroll
    for (int i = 0; i < 4; i++) {
        int idx = i * 256 + tid;
        int r = idx >> 3, c8 = (idx & 7) * 8;
        cp16(qs_u + (uint32_t)(r * TS_H + c8) * 2u,
             base + (size_t)(qb * QT + r) * (3 * D_MODEL) + c8);
    }
    asm volatile("cp.async.commit_group;\n" ::: "memory");

    float o[8][4];
    #pragma unroll
    for (int nt = 0; nt < 8; nt++)
        #pragma unroll
        for (int r = 0; r < 4; r++) o[nt][r] = 0.0f;
    float m0 = -INFINITY, m1 = -INFINITY, l0 = 0.0f, l1 = 0.0f;

    int qrow_lo = qb * QT + warp * 16;
    int kb_end = 2 * qb + 1;

    int tp = tid & 31;
    int dgrp = tid >> 5;

    for (int kb = 0; kb <= kb_end; kb++) {
        __syncthreads();
        #pragma unroll
        for (int i = 0; i < 2; i++) {
            int idx = i * 256 + tid;
            int r = idx >> 3, c8 = (idx & 7) * 8;
            cp16(ks_u + (uint32_t)(r * TS_H + c8) * 2u,
                 base + D_MODEL + (size_t)(kb * KT + r) * (3 * D_MODEL) + c8);
        }
        asm volatile("cp.async.commit_group;\n" ::: "memory");

        __half2 va[4], vb[4];
        {
            const __half* v0r = base + 2 * D_MODEL + (size_t)(kb * KT + 2 * tp) * (3 * D_MODEL);
            const __half* v1r = v0r + 3 * D_MODEL;
            #pragma unroll
            for (int j = 0; j < 4; j++) {
                int d = dgrp * 8 + 2 * j;
                va[j] = *(const __half2*)(v0r + d);
                vb[j] = *(const __half2*)(v1r + d);
            }
        }
        asm volatile("cp.async.wait_group 0;\n" ::: "memory");
        __syncthreads();

        bool active = (kb * 64 <= qrow_lo + 15);
        float corr0 = 1.0f, corr1 = 1.0f;

        if (active) {
            float s[8][4];
            #pragma unroll
            for (int nt = 0; nt < 8; nt++)
                #pragma unroll
                for (int r = 0; r < 4; r++) s[nt][r] = 0.0f;

            int mrow = warp * 16 + g;
            #pragma unroll
            for (int ks = 0; ks < 4; ks++) {
                uint32_t a[4], bb[8][2];
                a[0] = Qsw[mrow * 36 + ks * 8 + tig];
                a[1] = Qsw[(mrow + 8) * 36 + ks * 8 + tig];
                a[2] = Qsw[mrow * 36 + ks * 8 + 4 + tig];
                a[3] = Qsw[(mrow + 8) * 36 + ks * 8 + 4 + tig];
                #pragma unroll
                for (int nt = 0; nt < 8; nt++) {
                    bb[nt][0] = Ksw[(nt * 8 + g) * 36 + ks * 8 + tig];
                    bb[nt][1] = Ksw[(nt * 8 + g) * 36 + ks * 8 + 4 + tig];
                }
                #pragma unroll
                for (int nt = 0; nt < 8; nt++) MMA_F16(s[nt], a, bb[nt]);
            }

            const float scale = 0.125f;
            int q0 = qb * QT + warp * 16 + g;
            int q1 = q0 + 8;
            bool diag = (kb * 64 + 63 > qrow_lo);
            #pragma unroll
            for (int nt = 0; nt < 8; nt++) {
                int key = kb * 64 + nt * 8 + 2 * tig;
                s[nt][0] *= scale; s[nt][1] *= scale;
                s[nt][2] *= scale; s[nt][3] *= scale;
                if (diag) {
                    if (key     > q0) s[nt][0] = -1e30f;
                    if (key + 1 > q0) s[nt][1] = -1e30f;
                    if (key     > q1) s[nt][2] = -1e30f;
                    if (key + 1 > q1) s[nt][3] = -1e30f;
                }
            }

            float rmax0 = -INFINITY, rmax1 = -INFINITY;
            #pragma unroll
            for (int nt = 0; nt < 8; nt++) {
                rmax0 = fmaxf(rmax0, fmaxf(s[nt][0], s[nt][1]));
                rmax1 = fmaxf(rmax1, fmaxf(s[nt][2], s[nt][3]));
            }
            rmax0 = fmaxf(rmax0, __shfl_xor_sync(0xffffffffu, rmax0, 1));
            rmax0 = fmaxf(rmax0, __shfl_xor_sync(0xffffffffu, rmax0, 2));
            rmax1 = fmaxf(rmax1, __shfl_xor_sync(0xffffffffu, rmax1, 1));
            rmax1 = fmaxf(rmax1, __shfl_xor_sync(0xffffffffu, rmax1, 2));

            float mn0 = fmaxf(m0, rmax0), mn1 = fmaxf(m1, rmax1);
            corr0 = __expf(m0 - mn0);
            corr1 = __expf(m1 - mn1);

            float rs0 = 0.0f, rs1 = 0.0f;
            #pragma unroll
            for (int nt = 0; nt < 8; nt++) {
                s[nt][0] = __expf(s[nt][0] - mn0);
                s[nt][1] = __expf(s[nt][1] - mn0);
                s[nt][2] = __expf(s[nt][2] - mn1);
                s[nt][3] = __expf(s[nt][3] - mn1);
                rs0 += s[nt][0] + s[nt][1];
                rs1 += s[nt][2] + s[nt][3];
            }
            rs0 += __shfl_xor_sync(0xffffffffu, rs0, 1);
            rs0 += __shfl_xor_sync(0xffffffffu, rs0, 2);
            rs1 += __shfl_xor_sync(0xffffffffu, rs1, 1);
            rs1 += __shfl_xor_sync(0xffffffffu, rs1, 2);

            l0 = l0 * corr0 + rs0;  m0 = mn0;
            l1 = l1 * corr1 + rs1;  m1 = mn1;

            int pr0 = warp * 16 + g;
            #pragma unroll
            for (int nt = 0; nt < 8; nt++) {
                __half2 p0 = __floats2half2_rn(s[nt][0], s[nt][1]);
                __half2 p1 = __floats2half2_rn(s[nt][2], s[nt][3]);
                Psw[pr0 * 36 + nt * 4 + tig]       = *(uint32_t*)&p0;
                Psw[(pr0 + 8) * 36 + nt * 4 + tig] = *(uint32_t*)&p1;
            }
        }

        #pragma unroll
        for (int j = 0; j < 4; j++) {
            int d = dgrp * 8 + 2 * j;
            __half2 lo = __lows2half2(va[j], vb[j]);
            __half2 hi = __highs2half2(va[j], vb[j]);
            Vtw[d * 36 + tp]       = *(uint32_t*)&lo;
            Vtw[(d + 1) * 36 + tp] = *(uint32_t*)&hi;
        }
        __syncthreads();

        if (active) {
            #pragma unroll
            for (int nt = 0; nt < 8; nt++) {
                o[nt][0] *= corr0; o[nt][1] *= corr0;
                o[nt][2] *= corr1; o[nt][3] *= corr1;
            }
            int pr0 = warp * 16 + g;
            #pragma unroll
            for (int ks = 0; ks < 4; ks++) {
                uint32_t a[4], bb[8][2];
                a[0] = Psw[pr0 * 36 + ks * 8 + tig];
                a[1] = Psw[(pr0 + 8) * 36 + ks * 8 + tig];
                a[2] = Psw[pr0 * 36 + ks * 8 + 4 + tig];
                a[3] = Psw[(pr0 + 8) * 36 + ks * 8 + 4 + tig];
                #pragma unroll
                for (int nt = 0; nt < 8; nt++) {
                    bb[nt][0] = Vw[(nt * 8 + g) * 36 + ks * 8 + tig];
                    bb[nt][1] = Vw[(nt * 8 + g) * 36 + ks * 8 + 4 + tig];
                }
                #pragma unroll
                for (int nt = 0; nt < 8; nt++) MMA_F16(o[nt], a, bb[nt]);
            }
        }
    }

    float il0 = 1.0f / l0, il1 = 1.0f / l1;
    size_t row0 = (size_t)(b * SEQ + qb * QT + warp * 16 + g);
    #pragma unroll
    for (int nt = 0; nt < 8; nt++) {
        int col = h * HD + nt * 8 + 2 * tig;
        *(__half2*)(out + row0 * D_MODEL + col) =
            __floats2half2_rn(o[nt][0] * il0, o[nt][1] * il0);
        *(__half2*)(out + (row0 + 8) * D_MODEL + col) =
            __floats2half2_rn(o[nt][2] * il1, o[nt][3] * il1);
    }
}

// ---------------- launch (multi-stream fork/join, graph-capturable) ----------------
extern "C" void kernel_launch(void* const* d_in, const int* in_sizes, int n_in,
                              void* d_out, int out_size)
{
    const float* x        = (const float*)d_in[0];
    const float* ln1_w    = (const float*)d_in[1];
    const float* ln1_b    = (const float*)d_in[2];
    const float* c_attn_w = (const float*)d_in[3];
    const float* c_attn_b = (const float*)d_in[4];
    const float* c_proj_w = (const float*)d_in[5];
    const float* c_proj_b = (const float*)d_in[6];
    const float* ln2_w    = (const float*)d_in[7];
    const float* ln2_b    = (const float*)d_in[8];
    const float* fc_w     = (const float*)d_in[9];
    const float* fc_b     = (const float*)d_in[10];
    const float* proj_w   = (const float*)d_in[11];
    const float* proj_b   = (const float*)d_in[12];
    float* out = (float*)d_out;

    float  *x1;
    __half *qkv, *ln1h, *attnh, *ln2h, *hh, *wattn, *wproj, *wfc, *wproj2;
    cudaGetSymbolAddress((void**)&x1,    g_x1);
    cudaGetSymbolAddress((void**)&qkv,   g_qkv);
    cudaGetSymbolAddress((void**)&ln1h,  g_ln1h);
    cudaGetSymbolAddress((void**)&attnh, g_attnh);
    cudaGetSymbolAddress((void**)&ln2h,  g_ln2h);
    cudaGetSymbolAddress((void**)&hh,    g_hh);
    cudaGetSymbolAddress((void**)&wattn, g_wattn);
    cudaGetSymbolAddress((void**)&wproj, g_wproj);
    cudaGetSymbolAddress((void**)&wfc,   g_wfc);
    cudaGetSymbolAddress((void**)&wproj2, g_wproj2);

    static cudaStream_t s_w = nullptr, s_l = nullptr;
    static cudaEvent_t ev_fork = nullptr, ev_w = nullptr, ev_ln = nullptr;
    static bool attr_done = false;
    if (!attr_done) {
        cudaFuncSetAttribute(gemm_fp16<0>, cudaFuncAttributeMaxDynamicSharedMemorySize, GEMM_SMEM_BYTES);
        cudaFuncSetAttribute(gemm_fp16<1>, cudaFuncAttributeMaxDynamicSharedMemorySize, GEMM_SMEM_BYTES);
        cudaFuncSetAttribute(gemm_fp16<2>, cudaFuncAttributeMaxDynamicSharedMemorySize, GEMM_SMEM_BYTES);
        cudaFuncSetAttribute(attn_tc,      cudaFuncAttributeMaxDynamicSharedMemorySize, ATTN_SMEM);
        cudaStreamCreateWithFlags(&s_w, cudaStreamNonBlocking);
        cudaStreamCreateWithFlags(&s_l, cudaStreamNonBlocking);
        cudaEventCreateWithFlags(&ev_fork, cudaEventDisableTiming);
        cudaEventCreateWithFlags(&ev_w,    cudaEventDisableTiming);
        cudaEventCreateWithFlags(&ev_ln,   cudaEventDisableTiming);
        attr_done = true;
    }

    // ---- fork ----
    cudaEventRecord(ev_fork, 0);
    cudaStreamWaitEvent(s_w, ev_fork, 0);
    cudaStreamWaitEvent(s_l, ev_fork, 0);

    ln_kernel<<<NTOK, 256, 0, s_l>>>(x, ln1_w, ln1_b, ln1h);
    cudaEventRecord(ev_ln, s_l);

    wconv<<<(D_MODEL / 2 * D_MODEL / 4 + 255) / 256, 256, 0, s_w>>>(c_proj_w, wproj, D_MODEL, D_MODEL);
    wconv<<<(D_MODEL / 2 * 4 * D_MODEL / 4 + 255) / 256, 256, 0, s_w>>>(fc_w, wfc, D_MODEL, 4 * D_MODEL);
    wconv<<<(4 * D_MODEL / 2 * D_MODEL / 4 + 255) / 256, 256, 0, s_w>>>(proj_w, wproj2, 4 * D_MODEL, D_MODEL);
    cudaEventRecord(ev_w, s_w);

    wconv<<<(D_MODEL / 2 * 3 * D_MODEL / 4 + 255) / 256, 256>>>(c_attn_w, wattn, D_MODEL, 3 * D_MODEL);
    cudaStreamWaitEvent(0, ev_ln, 0);
    gemm_fp16<0><<<dim3(3 * D_MODEL / BN, NTOK / BM), 512, GEMM_SMEM_BYTES>>>(
        ln1h, wattn, c_attn_b, nullptr, nullptr, qkv, NTOK, 3 * D_MODEL, D_MODEL);
    attn_tc<<<dim3(SEQ / QT, NHEAD, BATCH), 256, ATTN_SMEM>>>(qkv, attnh);

    cudaStreamWaitEvent(0, ev_w, 0);
    gemm_fp16<1><<<dim3(D_MODEL / BN, NTOK / BM), 512, GEMM_SMEM_BYTES>>>(
        attnh, wproj, c_proj_b, x, x1, nullptr, NTOK, D_MODEL, D_MODEL);
    ln_kernel<<<NTOK, 256>>>(x1, ln2_w, ln2_b, ln2h);
    gemm_fp16<2><<<dim3(4 * D_MODEL / BN, NTOK / BM), 512, GEMM_SMEM_BYTES>>>(
        ln2h, wfc, fc_b, nullptr, nullptr, hh, NTOK, 4 * D_MODEL, D_MODEL);
    gemm_fp16<1><<<dim3(D_MODEL / BN, NTOK / BM), 512, GEMM_SMEM_BYTES>>>(
        hh, wproj2, proj_b, x1, out, nullptr, NTOK, D_MODEL, 4 * D_MODEL);
}

// round 16
// speedup vs baseline: 1.1873x; 1.1873x over previous
#include <cuda_runtime.h>
#include <cuda_fp16.h>
#include <math.h>
#include <stdint.h>

#define D_MODEL 1024
#define SEQ     2048
#define BATCH   2
#define NTOK    4096
#define NHEAD   16
#define HD      64

// ---------------- scratch ----------------
__device__ float  g_x1  [NTOK * D_MODEL];
__device__ __half g_qkv [NTOK * 3 * D_MODEL];
__device__ __half g_ln1h[NTOK * D_MODEL];
__device__ __half g_attnh[NTOK * D_MODEL];
__device__ __half g_ln2h[NTOK * D_MODEL];
__device__ __half g_hh  [NTOK * 4 * D_MODEL];
// fp16 weights, k-pair interleaved: w16[((k>>1)*N + n)*2 + (k&1)]
__device__ __half g_wattn [D_MODEL * 3 * D_MODEL];
__device__ __half g_wproj [D_MODEL * D_MODEL];
__device__ __half g_wfc   [D_MODEL * 4 * D_MODEL];
__device__ __half g_wproj2[4 * D_MODEL * D_MODEL];

// ---------------- weight fp32 -> fp16 interleaved (vectorized) ----------------
__global__ __launch_bounds__(256) void wconv(const float* __restrict__ w,
                                             __half* __restrict__ o,
                                             int K, int N)
{
    int idx = blockIdx.x * 256 + threadIdx.x;   // over (K/2)*(N/4)
    int nq4 = N >> 2;
    if (idx >= (K / 2) * nq4) return;
    int kp = idx / nq4, n = (idx - kp * nq4) * 4;
    float4 lo = *(const float4*)(w + (size_t)(2 * kp) * N + n);
    float4 hi = *(const float4*)(w + (size_t)(2 * kp + 1) * N + n);
    __half2 h0 = __floats2half2_rn(lo.x, hi.x);
    __half2 h1 = __floats2half2_rn(lo.y, hi.y);
    __half2 h2 = __floats2half2_rn(lo.z, hi.z);
    __half2 h3 = __floats2half2_rn(lo.w, hi.w);
    uint4 pack;
    pack.x = *(uint32_t*)&h0; pack.y = *(uint32_t*)&h1;
    pack.z = *(uint32_t*)&h2; pack.w = *(uint32_t*)&h3;
    *(uint4*)(o + ((size_t)kp * N + n) * 2) = pack;
}

// ---------------- LayerNorm -> fp16 ----------------
__global__ __launch_bounds__(256) void ln_kernel(const float* __restrict__ x,
                                                 const float* __restrict__ w,
                                                 const float* __restrict__ b,
                                                 __half* __restrict__ y)
{
    int row = blockIdx.x;
    int tid = threadIdx.x;
    const float4* xr = (const float4*)(x + (size_t)row * D_MODEL);
    float4 v = xr[tid];

    __shared__ float red[8];

    float s = v.x + v.y + v.z + v.w;
    #pragma unroll
    for (int o = 16; o > 0; o >>= 1) s += __shfl_xor_sync(0xffffffffu, s, o);
    if ((tid & 31) == 0) red[tid >> 5] = s;
    __syncthreads();
    float tot = red[0] + red[1] + red[2] + red[3] + red[4] + red[5] + red[6] + red[7];
    float mean = tot * (1.0f / 1024.0f);

    float a0 = v.x - mean, a1 = v.y - mean, a2 = v.z - mean, a3 = v.w - mean;
    __syncthreads();
    float q = a0*a0 + a1*a1 + a2*a2 + a3*a3;
    #pragma unroll
    for (int o = 16; o > 0; o >>= 1) q += __shfl_xor_sync(0xffffffffu, q, o);
    if ((tid & 31) == 0) red[tid >> 5] = q;
    __syncthreads();
    float ssq = red[0] + red[1] + red[2] + red[3] + red[4] + red[5] + red[6] + red[7];

    float sd  = sqrtf(ssq * (1.0f / 1023.0f));
    float inv = 1.0f / (sd + 1e-5f);

    float4 wv = ((const float4*)w)[tid];
    float4 bv = ((const float4*)b)[tid];
    __half2* yr = (__half2*)(y + (size_t)row * D_MODEL);
    yr[2 * tid]     = __floats2half2_rn(wv.x * (a0 * inv) + bv.x,
                                        wv.y * (a1 * inv) + bv.y);
    yr[2 * tid + 1] = __floats2half2_rn(wv.z * (a2 * inv) + bv.z,
                                        wv.w * (a3 * inv) + bv.w);
}

__device__ __forceinline__ float gelu_f(float x)
{
    float x3 = x * x * x;
    return 0.5f * x * (1.0f + tanhf(0.7978845608028654f * (x + 0.044715f * x3)));
}

__device__ __forceinline__ void cp16(uint32_t dst, const void* src)
{
    asm volatile("cp.async.cg.shared.global [%0], [%1], 16;\n" :: "r"(dst), "l"(src));
}

#define MMA_F16(c, a, b) \
    asm volatile( \
        "mma.sync.aligned.m16n8k16.row.col.f32.f16.f16.f32 " \
        "{%0,%1,%2,%3}, {%4,%5,%6,%7}, {%8,%9}, {%0,%1,%2,%3};\n" \
        : "+f"((c)[0]), "+f"((c)[1]), "+f"((c)[2]), "+f"((c)[3]) \
        : "r"((a)[0]), "r"((a)[1]), "r"((a)[2]), "r"((a)[3]), \
          "r"((b)[0]), "r"((b)[1]))

#define LDSM_X4(r0, r1, r2, r3, addr) \
    asm volatile("ldmatrix.sync.aligned.m8n8.x4.shared.b16 {%0,%1,%2,%3}, [%4];" \
        : "=r"(r0), "=r"(r1), "=r"(r2), "=r"(r3) : "r"(addr))

// ---------------- fp16 GEMM 128x128x64, 3-stage cp.async ----------------
// Same warp layout / inner body as the 620us best; K-chunk doubled to 64.
#define BM 128
#define BN 128
#define BKT 64
#define A_ROW_H 72                                  // 64 halfs + pad (36 words, %32==4)
#define A_STAGE_BYTES (BM * A_ROW_H * 2)            // 18432
#define B_ROW_W 136
#define B_STAGE_BYTES (32 * B_ROW_W * 4)            // 17408 (32 kpair rows)
#define STAGE_BYTES (A_STAGE_BYTES + B_STAGE_BYTES) // 35840
#define GEMM_SMEM_BYTES (3 * STAGE_BYTES)           // 107520

// MODE 0: qkv(half) = A@B + bias ; MODE 1: C = res + A@B + bias (fp32)
// MODE 2: Ch = gelu(A@B + bias) (fp16)
template<int MODE>
__global__ __launch_bounds__(256, 2) void gemm_fp16(const __half* __restrict__ A,
                                                    const __half* __restrict__ Bw16,
                                                    const float* __restrict__ bias,
                                                    const float* __restrict__ res,
                                                    float* __restrict__ C,
                                                    __half* __restrict__ Ch,
                                                    int M, int N, int K)
{
    extern __shared__ char smc[];
    int tid  = threadIdx.x;
    int bx = blockIdx.x, by = blockIdx.y;
    int warp = tid >> 5, lane = tid & 31;
    int wm = warp >> 2, wn = warp & 3;
    int g = lane >> 2, tig = lane & 3;

    int lr8  = lane & 7;
    int aoff = ((lane & 8) ? 8 : 0);
    int koff = ((lane & 16) ? 8 : 0);

    const __half* Ablk = A + (size_t)(by * BM) * K;
    const __half* Bblk = Bw16 + (size_t)(bx * BN) * 2;

    float c[4][4][4];
    #pragma unroll
    for (int mt = 0; mt < 4; mt++)
        #pragma unroll
        for (int nt = 0; nt < 4; nt++)
            #pragma unroll
            for (int r = 0; r < 4; r++) c[mt][nt][r] = 0.0f;

    const int iters = K / BKT;
    uint32_t smem_base = (uint32_t)__cvta_generic_to_shared(smc);

    auto load_stage = [&](int it, int buf) {
        uint32_t as = smem_base + (uint32_t)(buf * STAGE_BYTES);
        uint32_t bs = as + A_STAGE_BYTES;
        int k0 = it * BKT;
        // A: 128 rows x 64 halfs = 1024 x 16B chunks (4/thread)
        // B: 32 kpair rows x 128 words = 1024 x 16B chunks (4/thread)
        #pragma unroll
        for (int i = 0; i < 4; i++) {
            int q = tid + 256 * i;
            int ar = q >> 3, ac = (q & 7) * 8;
            cp16(as + (uint32_t)(ar * (A_ROW_H * 2) + ac * 2),
                 Ablk + (size_t)ar * K + k0 + ac);
            int br = q >> 5, bc = (q & 31) * 4;
            cp16(bs + (uint32_t)(br * (B_ROW_W * 4) + bc * 4),
                 Bblk + ((size_t)(k0 / 2 + br) * N + bc) * 2);
        }
        asm volatile("cp.async.commit_group;\n" ::: "memory");
    };

    load_stage(0, 0);
    if (iters > 1) load_stage(1, 1);

    for (int it = 0; it < iters; it++) {
        if (it + 1 < iters) asm volatile("cp.async.wait_group 1;\n" ::: "memory");
        else                asm volatile("cp.async.wait_group 0;\n" ::: "memory");
        __syncthreads();
        if (it + 2 < iters) load_stage(it + 2, (it + 2) % 3);

        const char* stg = smc + (it % 3) * STAGE_BYTES;
        const __half*  As = (const __half*)stg;
        const uint32_t* Bs = (const uint32_t*)(stg + A_STAGE_BYTES);

        #pragma unroll
        for (int s = 0; s < 4; s++) {          // four k16 steps per stage
            uint32_t a[4][4], b[4][2];
            #pragma unroll
            for (int mt = 0; mt < 4; mt++) {
                const __half* p = As + (size_t)(wm * 64 + mt * 16 + lr8 + aoff) * A_ROW_H
                                     + s * 16 + koff;
                uint32_t ad = (uint32_t)__cvta_generic_to_shared(p);
                LDSM_X4(a[mt][0], a[mt][1], a[mt][2], a[mt][3], ad);
            }
            #pragma unroll
            for (int nt = 0; nt < 4; nt++) {
                int n = wn * 32 + nt * 8 + g;
                b[nt][0] = Bs[(s * 8 + tig) * B_ROW_W + n];
                b[nt][1] = Bs[(s * 8 + 4 + tig) * B_ROW_W + n];
            }
            #pragma unroll
            for (int mt = 0; mt < 4; mt++)
                #pragma unroll
                for (int nt = 0; nt < 4; nt++)
                    MMA_F16(c[mt][nt], a[mt], b[nt]);
        }
    }

    #pragma unroll
    for (int mt = 0; mt < 4; mt++) {
        int row0 = by * BM + wm * 64 + mt * 16 + g;
        #pragma unroll
        for (int nt = 0; nt < 4; nt++) {
            int col = bx * BN + wn * 32 + nt * 8 + tig * 2;
            float b0 = __ldg(bias + col), b1 = __ldg(bias + col + 1);
            float v0 = c[mt][nt][0] + b0, v1 = c[mt][nt][1] + b1;
            float v2 = c[mt][nt][2] + b0, v3 = c[mt][nt][3] + b1;
            if (MODE == 0) {
                *(__half2*)(Ch + (size_t)row0 * N + col) = __floats2half2_rn(v0, v1);
                *(__half2*)(Ch + (size_t)(row0 + 8) * N + col) = __floats2half2_rn(v2, v3);
            }
            if (MODE == 1) {
                const float* r0 = res + (size_t)row0 * N + col;
                const float* r1 = res + (size_t)(row0 + 8) * N + col;
                *(float2*)(C + (size_t)row0 * N + col) =
                    make_float2(v0 + r0[0], v1 + r0[1]);
                *(float2*)(C + (size_t)(row0 + 8) * N + col) =
                    make_float2(v2 + r1[0], v3 + r1[1]);
            }
            if (MODE == 2) {
                *(__half2*)(Ch + (size_t)row0 * N + col) =
                    __floats2half2_rn(gelu_f(v0), gelu_f(v1));
                *(__half2*)(Ch + (size_t)(row0 + 8) * N + col) =
                    __floats2half2_rn(gelu_f(v2), gelu_f(v3));
            }
        }
    }
}

// ---------------- fp16 flash attention (R13 exact: V-hoist, single K buffer) ----------------
#define QT 128
#define KT 64
#define TS_H 72
#define ATTN_SMEM ((QT*TS_H + KT*TS_H + KT*TS_H + QT*TS_H) * 2)

__global__ __launch_bounds__(256, 2) void attn_tc(const __half* __restrict__ qkv,
                                                  __half* __restrict__ out)
{
    extern __shared__ __half smh[];
    __half* Qs = smh;                       // [128][72]
    __half* Ks = Qs + QT * TS_H;            // [64][72]
    __half* Vt = Ks + KT * TS_H;            // [64 d][72 keys]
    __half* Ps = Vt + KT * TS_H;            // [128][72]

    int tid = threadIdx.x, warp = tid >> 5, lane = tid & 31;
    int g = lane >> 2, tig = lane & 3;
    int qb = gridDim.x - 1 - blockIdx.x;
    int h = blockIdx.y, b = blockIdx.z;

    const __half* base = qkv + (size_t)b * SEQ * (3 * D_MODEL) + h * HD;

    uint32_t qs_u = (uint32_t)__cvta_generic_to_shared(Qs);
    uint32_t ks_u = (uint32_t)__cvta_generic_to_shared(Ks);
    uint32_t* Vtw = (uint32_t*)Vt;
    const uint32_t* Qsw = (const uint32_t*)Qs;
    const uint32_t* Ksw = (const uint32_t*)Ks;
    const uint32_t* Vw  = (const uint32_t*)Vt;
    uint32_t* Psw = (uint32_t*)Ps;

    #pragma unroll
    for (int i = 0; i < 4; i++) {
        int idx = i * 256 + tid;
        int r = idx >> 3, c8 = (idx & 7) * 8;
        cp16(qs_u + (uint32_t)(r * TS_H + c8) * 2u,
             base + (size_t)(qb * QT + r) * (3 * D_MODEL) + c8);
    }
    asm volatile("cp.async.commit_group;\n" ::: "memory");

    float o[8][4];
    #pragma unroll
    for (int nt = 0; nt < 8; nt++)
        #pragma unroll
        for (int r = 0; r < 4; r++) o[nt][r] = 0.0f;
    float m0 = -INFINITY, m1 = -INFINITY, l0 = 0.0f, l1 = 0.0f;

    int qrow_lo = qb * QT + warp * 16;
    int kb_end = 2 * qb + 1;

    int tp = tid & 31;
    int dgrp = tid >> 5;

    for (int kb = 0; kb <= kb_end; kb++) {
        __syncthreads();
        #pragma unroll
        for (int i = 0; i < 2; i++) {
            int idx = i * 256 + tid;
            int r = idx >> 3, c8 = (idx & 7) * 8;
            cp16(ks_u + (uint32_t)(r * TS_H + c8) * 2u,
                 base + D_MODEL + (size_t)(kb * KT + r) * (3 * D_MODEL) + c8);
        }
        asm volatile("cp.async.commit_group;\n" ::: "memory");

        __half2 va[4], vb[4];
        {
            const __half* v0r = base + 2 * D_MODEL + (size_t)(kb * KT + 2 * tp) * (3 * D_MODEL);
            const __half* v1r = v0r + 3 * D_MODEL;
            #pragma unroll
            for (int j = 0; j < 4; j++) {
                int d = dgrp * 8 + 2 * j;
                va[j] = *(const __half2*)(v0r + d);
                vb[j] = *(const __half2*)(v1r + d);
            }
        }
        asm volatile("cp.async.wait_group 0;\n" ::: "memory");
        __syncthreads();

        bool active = (kb * 64 <= qrow_lo + 15);
        float corr0 = 1.0f, corr1 = 1.0f;

        if (active) {
            float s[8][4];
            #pragma unroll
            for (int nt = 0; nt < 8; nt++)
                #pragma unroll
                for (int r = 0; r < 4; r++) s[nt][r] = 0.0f;

            int mrow = warp * 16 + g;
            #pragma unroll
            for (int ks = 0; ks < 4; ks++) {
                uint32_t a[4], bb[8][2];
                a[0] = Qsw[mrow * 36 + ks * 8 + tig];
                a[1] = Qsw[(mrow + 8) * 36 + ks * 8 + tig];
                a[2] = Qsw[mrow * 36 + ks * 8 + 4 + tig];
                a[3] = Qsw[(mrow + 8) * 36 + ks * 8 + 4 + tig];
                #pragma unroll
                for (int nt = 0; nt < 8; nt++) {
                    bb[nt][0] = Ksw[(nt * 8 + g) * 36 + ks * 8 + tig];
                    bb[nt][1] = Ksw[(nt * 8 + g) * 36 + ks * 8 + 4 + tig];
                }
                #pragma unroll
                for (int nt = 0; nt < 8; nt++) MMA_F16(s[nt], a, bb[nt]);
            }

            const float scale = 0.125f;
            int q0 = qb * QT + warp * 16 + g;
            int q1 = q0 + 8;
            bool diag = (kb * 64 + 63 > qrow_lo);
            #pragma unroll
            for (int nt = 0; nt < 8; nt++) {
                int key = kb * 64 + nt * 8 + 2 * tig;
                s[nt][0] *= scale; s[nt][1] *= scale;
                s[nt][2] *= scale; s[nt][3] *= scale;
                if (diag) {
                    if (key     > q0) s[nt][0] = -1e30f;
                    if (key + 1 > q0) s[nt][1] = -1e30f;
                    if (key     > q1) s[nt][2] = -1e30f;
                    if (key + 1 > q1) s[nt][3] = -1e30f;
                }
            }

            float rmax0 = -INFINITY, rmax1 = -INFINITY;
            #pragma unroll
            for (int nt = 0; nt < 8; nt++) {
                rmax0 = fmaxf(rmax0, fmaxf(s[nt][0], s[nt][1]));
                rmax1 = fmaxf(rmax1, fmaxf(s[nt][2], s[nt][3]));
            }
            rmax0 = fmaxf(rmax0, __shfl_xor_sync(0xffffffffu, rmax0, 1));
            rmax0 = fmaxf(rmax0, __shfl_xor_sync(0xffffffffu, rmax0, 2));
            rmax1 = fmaxf(rmax1, __shfl_xor_sync(0xffffffffu, rmax1, 1));
            rmax1 = fmaxf(rmax1, __shfl_xor_sync(0xffffffffu, rmax1, 2));

            float mn0 = fmaxf(m0, rmax0), mn1 = fmaxf(m1, rmax1);
            corr0 = __expf(m0 - mn0);
            corr1 = __expf(m1 - mn1);

            float rs0 = 0.0f, rs1 = 0.0f;
            #pragma unroll
            for (int nt = 0; nt < 8; nt++) {
                s[nt][0] = __expf(s[nt][0] - mn0);
                s[nt][1] = __expf(s[nt][1] - mn0);
                s[nt][2] = __expf(s[nt][2] - mn1);
                s[nt][3] = __expf(s[nt][3] - mn1);
                rs0 += s[nt][0] + s[nt][1];
                rs1 += s[nt][2] + s[nt][3];
            }
            rs0 += __shfl_xor_sync(0xffffffffu, rs0, 1);
            rs0 += __shfl_xor_sync(0xffffffffu, rs0, 2);
            rs1 += __shfl_xor_sync(0xffffffffu, rs1, 1);
            rs1 += __shfl_xor_sync(0xffffffffu, rs1, 2);

            l0 = l0 * corr0 + rs0;  m0 = mn0;
            l1 = l1 * corr1 + rs1;  m1 = mn1;

            int pr0 = warp * 16 + g;
            #pragma unroll
            for (int nt = 0; nt < 8; nt++) {
                __half2 p0 = __floats2half2_rn(s[nt][0], s[nt][1]);
                __half2 p1 = __floats2half2_rn(s[nt][2], s[nt][3]);
                Psw[pr0 * 36 + nt * 4 + tig]       = *(uint32_t*)&p0;
                Psw[(pr0 + 8) * 36 + nt * 4 + tig] = *(uint32_t*)&p1;
            }
        }

        #pragma unroll
        for (int j = 0; j < 4; j++) {
            int d = dgrp * 8 + 2 * j;
            __half2 lo = __lows2half2(va[j], vb[j]);
            __half2 hi = __highs2half2(va[j], vb[j]);
            Vtw[d * 36 + tp]       = *(uint32_t*)&lo;
            Vtw[(d + 1) * 36 + tp] = *(uint32_t*)&hi;
        }
        __syncthreads();

        if (active) {
            #pragma unroll
            for (int nt = 0; nt < 8; nt++) {
                o[nt][0] *= corr0; o[nt][1] *= corr0;
                o[nt][2] *= corr1; o[nt][3] *= corr1;
            }
            int pr0 = warp * 16 + g;
            #pragma unroll
            for (int ks = 0; ks < 4; ks++) {
                uint32_t a[4], bb[8][2];
                a[0] = Psw[pr0 * 36 + ks * 8 + tig];
                a[1] = Psw[(pr0 + 8) * 36 + ks * 8 + tig];
                a[2] = Psw[pr0 * 36 + ks * 8 + 4 + tig];
                a[3] = Psw[(pr0 + 8) * 36 + ks * 8 + 4 + tig];
                #pragma unroll
                for (int nt = 0; nt < 8; nt++) {
                    bb[nt][0] = Vw[(nt * 8 + g) * 36 + ks * 8 + tig];
                    bb[nt][1] = Vw[(nt * 8 + g) * 36 + ks * 8 + 4 + tig];
                }
                #pragma unroll
                for (int nt = 0; nt < 8; nt++) MMA_F16(o[nt], a, bb[nt]);
            }
        }
    }

    float il0 = 1.0f / l0, il1 = 1.0f / l1;
    size_t row0 = (size_t)(b * SEQ + qb * QT + warp * 16 + g);
    #pragma unroll
    for (int nt = 0; nt < 8; nt++) {
        int col = h * HD + nt * 8 + 2 * tig;
        *(__half2*)(out + row0 * D_MODEL + col) =
            __floats2half2_rn(o[nt][0] * il0, o[nt][1] * il0);
        *(__half2*)(out + (row0 + 8) * D_MODEL + col) =
            __floats2half2_rn(o[nt][2] * il1, o[nt][3] * il1);
    }
}

// ---------------- launch (multi-stream fork/join, graph-capturable) ----------------
extern "C" void kernel_launch(void* const* d_in, const int* in_sizes, int n_in,
                              void* d_out, int out_size)
{
    const float* x        = (const float*)d_in[0];
    const float* ln1_w    = (const float*)d_in[1];
    const float* ln1_b    = (const float*)d_in[2];
    const float* c_attn_w = (const float*)d_in[3];
    const float* c_attn_b = (const float*)d_in[4];
    const float* c_proj_w = (const float*)d_in[5];
    const float* c_proj_b = (const float*)d_in[6];
    const float* ln2_w    = (const float*)d_in[7];
    const float* ln2_b    = (const float*)d_in[8];
    const float* fc_w     = (const float*)d_in[9];
    const float* fc_b     = (const float*)d_in[10];
    const float* proj_w   = (const float*)d_in[11];
    const float* proj_b   = (const float*)d_in[12];
    float* out = (float*)d_out;

    float  *x1;
    __half *qkv, *ln1h, *attnh, *ln2h, *hh, *wattn, *wproj, *wfc, *wproj2;
    cudaGetSymbolAddress((void**)&x1,    g_x1);
    cudaGetSymbolAddress((void**)&qkv,   g_qkv);
    cudaGetSymbolAddress((void**)&ln1h,  g_ln1h);
    cudaGetSymbolAddress((void**)&attnh, g_attnh);
    cudaGetSymbolAddress((void**)&ln2h,  g_ln2h);
    cudaGetSymbolAddress((void**)&hh,    g_hh);
    cudaGetSymbolAddress((void**)&wattn, g_wattn);
    cudaGetSymbolAddress((void**)&wproj, g_wproj);
    cudaGetSymbolAddress((void**)&wfc,   g_wfc);
    cudaGetSymbolAddress((void**)&wproj2, g_wproj2);

    static cudaStream_t s_w = nullptr, s_l = nullptr;
    static cudaEvent_t ev_fork = nullptr, ev_w = nullptr, ev_ln = nullptr;
    static bool attr_done = false;
    if (!attr_done) {
        cudaFuncSetAttribute(gemm_fp16<0>, cudaFuncAttributeMaxDynamicSharedMemorySize, GEMM_SMEM_BYTES);
        cudaFuncSetAttribute(gemm_fp16<1>, cudaFuncAttributeMaxDynamicSharedMemorySize, GEMM_SMEM_BYTES);
        cudaFuncSetAttribute(gemm_fp16<2>, cudaFuncAttributeMaxDynamicSharedMemorySize, GEMM_SMEM_BYTES);
        cudaFuncSetAttribute(attn_tc,      cudaFuncAttributeMaxDynamicSharedMemorySize, ATTN_SMEM);
        cudaStreamCreateWithFlags(&s_w, cudaStreamNonBlocking);
        cudaStreamCreateWithFlags(&s_l, cudaStreamNonBlocking);
        cudaEventCreateWithFlags(&ev_fork, cudaEventDisableTiming);
        cudaEventCreateWithFlags(&ev_w,    cudaEventDisableTiming);
        cudaEventCreateWithFlags(&ev_ln,   cudaEventDisableTiming);
        attr_done = true;
    }

    // ---- fork ----
    cudaEventRecord(ev_fork, 0);
    cudaStreamWaitEvent(s_w, ev_fork, 0);
    cudaStreamWaitEvent(s_l, ev_fork, 0);

    ln_kernel<<<NTOK, 256, 0, s_l>>>(x, ln1_w, ln1_b, ln1h);
    cudaEventRecord(ev_ln, s_l);

    wconv<<<(D_MODEL / 2 * D_MODEL / 4 + 255) / 256, 256, 0, s_w>>>(c_proj_w, wproj, D_MODEL, D_MODEL);
    wconv<<<(D_MODEL / 2 * 4 * D_MODEL / 4 + 255) / 256, 256, 0, s_w>>>(fc_w, wfc, D_MODEL, 4 * D_MODEL);
    wconv<<<(4 * D_MODEL / 2 * D_MODEL / 4 + 255) / 256, 256, 0, s_w>>>(proj_w, wproj2, 4 * D_MODEL, D_MODEL);
    cudaEventRecord(ev_w, s_w);

    wconv<<<(D_MODEL / 2 * 3 * D_MODEL / 4 + 255) / 256, 256>>>(c_attn_w, wattn, D_MODEL, 3 * D_MODEL);
    cudaStreamWaitEvent(0, ev_ln, 0);
    gemm_fp16<0><<<dim3(3 * D_MODEL / BN, NTOK / BM), 256, GEMM_SMEM_BYTES>>>(
        ln1h, wattn, c_attn_b, nullptr, nullptr, qkv, NTOK, 3 * D_MODEL, D_MODEL);
    attn_tc<<<dim3(SEQ / QT, NHEAD, BATCH), 256, ATTN_SMEM>>>(qkv, attnh);

    cudaStreamWaitEvent(0, ev_w, 0);
    gemm_fp16<1><<<dim3(D_MODEL / BN, NTOK / BM), 256, GEMM_SMEM_BYTES>>>(
        attnh, wproj, c_proj_b, x, x1, nullptr, NTOK, D_MODEL, D_MODEL);
    ln_kernel<<<NTOK, 256>>>(x1, ln2_w, ln2_b, ln2h);
    gemm_fp16<2><<<dim3(4 * D_MODEL / BN, NTOK / BM), 256, GEMM_SMEM_BYTES>>>(
        ln2h, wfc, fc_b, nullptr, nullptr, hh, NTOK, 4 * D_MODEL, D_MODEL);
    gemm_fp16<1><<<dim3(D_MODEL / BN, NTOK / BM), 256, GEMM_SMEM_BYTES>>>(
        hh, wproj2, proj_b, x1, out, nullptr, NTOK, D_MODEL, 4 * D_MODEL);
}

// round 17
// speedup vs baseline: 1.2164x; 1.0245x over previous
#include <cuda_runtime.h>
#include <cuda_fp16.h>
#include <math.h>
#include <stdint.h>

#define D_MODEL 1024
#define SEQ     2048
#define BATCH   2
#define NTOK    4096
#define NHEAD   16
#define HD      64

// ---------------- scratch ----------------
__device__ float  g_x1  [NTOK * D_MODEL];
__device__ __half g_qkv [NTOK * 3 * D_MODEL];
__device__ __half g_ln1h[NTOK * D_MODEL];
__device__ __half g_attnh[NTOK * D_MODEL];
__device__ __half g_ln2h[NTOK * D_MODEL];
__device__ __half g_hh  [NTOK * 4 * D_MODEL];
// fp16 weights, k-pair interleaved: w16[((k>>1)*N + n)*2 + (k&1)]
__device__ __half g_wattn [D_MODEL * 3 * D_MODEL];
__device__ __half g_wproj [D_MODEL * D_MODEL];
__device__ __half g_wfc   [D_MODEL * 4 * D_MODEL];
__device__ __half g_wproj2[4 * D_MODEL * D_MODEL];

// ---------------- weight fp32 -> fp16 interleaved (vectorized) ----------------
__global__ __launch_bounds__(256) void wconv(const float* __restrict__ w,
                                             __half* __restrict__ o,
                                             int K, int N)
{
    int idx = blockIdx.x * 256 + threadIdx.x;   // over (K/2)*(N/4)
    int nq4 = N >> 2;
    if (idx >= (K / 2) * nq4) return;
    int kp = idx / nq4, n = (idx - kp * nq4) * 4;
    float4 lo = *(const float4*)(w + (size_t)(2 * kp) * N + n);
    float4 hi = *(const float4*)(w + (size_t)(2 * kp + 1) * N + n);
    __half2 h0 = __floats2half2_rn(lo.x, hi.x);
    __half2 h1 = __floats2half2_rn(lo.y, hi.y);
    __half2 h2 = __floats2half2_rn(lo.z, hi.z);
    __half2 h3 = __floats2half2_rn(lo.w, hi.w);
    uint4 pack;
    pack.x = *(uint32_t*)&h0; pack.y = *(uint32_t*)&h1;
    pack.z = *(uint32_t*)&h2; pack.w = *(uint32_t*)&h3;
    *(uint4*)(o + ((size_t)kp * N + n) * 2) = pack;
}

// ---------------- LayerNorm -> fp16 ----------------
__global__ __launch_bounds__(256) void ln_kernel(const float* __restrict__ x,
                                                 const float* __restrict__ w,
                                                 const float* __restrict__ b,
                                                 __half* __restrict__ y)
{
    int row = blockIdx.x;
    int tid = threadIdx.x;
    const float4* xr = (const float4*)(x + (size_t)row * D_MODEL);
    float4 v = xr[tid];

    __shared__ float red[8];

    float s = v.x + v.y + v.z + v.w;
    #pragma unroll
    for (int o = 16; o > 0; o >>= 1) s += __shfl_xor_sync(0xffffffffu, s, o);
    if ((tid & 31) == 0) red[tid >> 5] = s;
    __syncthreads();
    float tot = red[0] + red[1] + red[2] + red[3] + red[4] + red[5] + red[6] + red[7];
    float mean = tot * (1.0f / 1024.0f);

    float a0 = v.x - mean, a1 = v.y - mean, a2 = v.z - mean, a3 = v.w - mean;
    __syncthreads();
    float q = a0*a0 + a1*a1 + a2*a2 + a3*a3;
    #pragma unroll
    for (int o = 16; o > 0; o >>= 1) q += __shfl_xor_sync(0xffffffffu, q, o);
    if ((tid & 31) == 0) red[tid >> 5] = q;
    __syncthreads();
    float ssq = red[0] + red[1] + red[2] + red[3] + red[4] + red[5] + red[6] + red[7];

    float sd  = sqrtf(ssq * (1.0f / 1023.0f));
    float inv = 1.0f / (sd + 1e-5f);

    float4 wv = ((const float4*)w)[tid];
    float4 bv = ((const float4*)b)[tid];
    __half2* yr = (__half2*)(y + (size_t)row * D_MODEL);
    yr[2 * tid]     = __floats2half2_rn(wv.x * (a0 * inv) + bv.x,
                                        wv.y * (a1 * inv) + bv.y);
    yr[2 * tid + 1] = __floats2half2_rn(wv.z * (a2 * inv) + bv.z,
                                        wv.w * (a3 * inv) + bv.w);
}

__device__ __forceinline__ float gelu_f(float x)
{
    float x3 = x * x * x;
    return 0.5f * x * (1.0f + tanhf(0.7978845608028654f * (x + 0.044715f * x3)));
}

__device__ __forceinline__ void cp16(uint32_t dst, const void* src)
{
    asm volatile("cp.async.cg.shared.global [%0], [%1], 16;\n" :: "r"(dst), "l"(src));
}

#define MMA_F16(c, a, b) \
    asm volatile( \
        "mma.sync.aligned.m16n8k16.row.col.f32.f16.f16.f32 " \
        "{%0,%1,%2,%3}, {%4,%5,%6,%7}, {%8,%9}, {%0,%1,%2,%3};\n" \
        : "+f"((c)[0]), "+f"((c)[1]), "+f"((c)[2]), "+f"((c)[3]) \
        : "r"((a)[0]), "r"((a)[1]), "r"((a)[2]), "r"((a)[3]), \
          "r"((b)[0]), "r"((b)[1]))

#define LDSM_X4(r0, r1, r2, r3, addr) \
    asm volatile("ldmatrix.sync.aligned.m8n8.x4.shared.b16 {%0,%1,%2,%3}, [%4];" \
        : "=r"(r0), "=r"(r1), "=r"(r2), "=r"(r3) : "r"(addr))

// ---------------- fp16 GEMM 128x128x64, 3-stage cp.async (R16 exact) ----------------
#define BM 128
#define BN 128
#define BKT 64
#define A_ROW_H 72
#define A_STAGE_BYTES (BM * A_ROW_H * 2)
#define B_ROW_W 136
#define B_STAGE_BYTES (32 * B_ROW_W * 4)
#define STAGE_BYTES (A_STAGE_BYTES + B_STAGE_BYTES)
#define GEMM_SMEM_BYTES (3 * STAGE_BYTES)

template<int MODE>
__global__ __launch_bounds__(256, 2) void gemm_fp16(const __half* __restrict__ A,
                                                    const __half* __restrict__ Bw16,
                                                    const float* __restrict__ bias,
                                                    const float* __restrict__ res,
                                                    float* __restrict__ C,
                                                    __half* __restrict__ Ch,
                                                    int M, int N, int K)
{
    extern __shared__ char smc[];
    int tid  = threadIdx.x;
    int bx = blockIdx.x, by = blockIdx.y;
    int warp = tid >> 5, lane = tid & 31;
    int wm = warp >> 2, wn = warp & 3;
    int g = lane >> 2, tig = lane & 3;

    int lr8  = lane & 7;
    int aoff = ((lane & 8) ? 8 : 0);
    int koff = ((lane & 16) ? 8 : 0);

    const __half* Ablk = A + (size_t)(by * BM) * K;
    const __half* Bblk = Bw16 + (size_t)(bx * BN) * 2;

    float c[4][4][4];
    #pragma unroll
    for (int mt = 0; mt < 4; mt++)
        #pragma unroll
        for (int nt = 0; nt < 4; nt++)
            #pragma unroll
            for (int r = 0; r < 4; r++) c[mt][nt][r] = 0.0f;

    const int iters = K / BKT;
    uint32_t smem_base = (uint32_t)__cvta_generic_to_shared(smc);

    auto load_stage = [&](int it, int buf) {
        uint32_t as = smem_base + (uint32_t)(buf * STAGE_BYTES);
        uint32_t bs = as + A_STAGE_BYTES;
        int k0 = it * BKT;
        #pragma unroll
        for (int i = 0; i < 4; i++) {
            int q = tid + 256 * i;
            int ar = q >> 3, ac = (q & 7) * 8;
            cp16(as + (uint32_t)(ar * (A_ROW_H * 2) + ac * 2),
                 Ablk + (size_t)ar * K + k0 + ac);
            int br = q >> 5, bc = (q & 31) * 4;
            cp16(bs + (uint32_t)(br * (B_ROW_W * 4) + bc * 4),
                 Bblk + ((size_t)(k0 / 2 + br) * N + bc) * 2);
        }
        asm volatile("cp.async.commit_group;\n" ::: "memory");
    };

    load_stage(0, 0);
    if (iters > 1) load_stage(1, 1);

    for (int it = 0; it < iters; it++) {
        if (it + 1 < iters) asm volatile("cp.async.wait_group 1;\n" ::: "memory");
        else                asm volatile("cp.async.wait_group 0;\n" ::: "memory");
        __syncthreads();
        if (it + 2 < iters) load_stage(it + 2, (it + 2) % 3);

        const char* stg = smc + (it % 3) * STAGE_BYTES;
        const __half*  As = (const __half*)stg;
        const uint32_t* Bs = (const uint32_t*)(stg + A_STAGE_BYTES);

        #pragma unroll
        for (int s = 0; s < 4; s++) {
            uint32_t a[4][4], b[4][2];
            #pragma unroll
            for (int mt = 0; mt < 4; mt++) {
                const __half* p = As + (size_t)(wm * 64 + mt * 16 + lr8 + aoff) * A_ROW_H
                                     + s * 16 + koff;
                uint32_t ad = (uint32_t)__cvta_generic_to_shared(p);
                LDSM_X4(a[mt][0], a[mt][1], a[mt][2], a[mt][3], ad);
            }
            #pragma unroll
            for (int nt = 0; nt < 4; nt++) {
                int n = wn * 32 + nt * 8 + g;
                b[nt][0] = Bs[(s * 8 + tig) * B_ROW_W + n];
                b[nt][1] = Bs[(s * 8 + 4 + tig) * B_ROW_W + n];
            }
            #pragma unroll
            for (int mt = 0; mt < 4; mt++)
                #pragma unroll
                for (int nt = 0; nt < 4; nt++)
                    MMA_F16(c[mt][nt], a[mt], b[nt]);
        }
    }

    #pragma unroll
    for (int mt = 0; mt < 4; mt++) {
        int row0 = by * BM + wm * 64 + mt * 16 + g;
        #pragma unroll
        for (int nt = 0; nt < 4; nt++) {
            int col = bx * BN + wn * 32 + nt * 8 + tig * 2;
            float b0 = __ldg(bias + col), b1 = __ldg(bias + col + 1);
            float v0 = c[mt][nt][0] + b0, v1 = c[mt][nt][1] + b1;
            float v2 = c[mt][nt][2] + b0, v3 = c[mt][nt][3] + b1;
            if (MODE == 0) {
                *(__half2*)(Ch + (size_t)row0 * N + col) = __floats2half2_rn(v0, v1);
                *(__half2*)(Ch + (size_t)(row0 + 8) * N + col) = __floats2half2_rn(v2, v3);
            }
            if (MODE == 1) {
                const float* r0 = res + (size_t)row0 * N + col;
                const float* r1 = res + (size_t)(row0 + 8) * N + col;
                *(float2*)(C + (size_t)row0 * N + col) =
                    make_float2(v0 + r0[0], v1 + r0[1]);
                *(float2*)(C + (size_t)(row0 + 8) * N + col) =
                    make_float2(v2 + r1[0], v3 + r1[1]);
            }
            if (MODE == 2) {
                *(__half2*)(Ch + (size_t)row0 * N + col) =
                    __floats2half2_rn(gelu_f(v0), gelu_f(v1));
                *(__half2*)(Ch + (size_t)(row0 + 8) * N + col) =
                    __floats2half2_rn(gelu_f(v2), gelu_f(v3));
            }
        }
    }
}

// ---------------- fp16 flash attention, paired 64-key tiles ----------------
// Tile count per block (2qb+2) is even -> process pairs with one sync set per pair.
#define QT 128
#define KT 64
#define TS_H 72
// Q + K[2] + Vt[2] + P
#define ATTN_SMEM ((QT*TS_H + 2*KT*TS_H + 2*KT*TS_H + QT*TS_H) * 2)

__global__ __launch_bounds__(256, 2) void attn_tc(const __half* __restrict__ qkv,
                                                  __half* __restrict__ out)
{
    extern __shared__ __half smh[];
    __half* Qs  = smh;                       // [128][72]
    __half* Ks0 = Qs + QT * TS_H;            // [2][64][72]
    __half* Vt0 = Ks0 + 2 * KT * TS_H;       // [2][64 d][72 keys]
    __half* Ps  = Vt0 + 2 * KT * TS_H;       // [128][72]

    int tid = threadIdx.x, warp = tid >> 5, lane = tid & 31;
    int g = lane >> 2, tig = lane & 3;
    int qb = gridDim.x - 1 - blockIdx.x;
    int h = blockIdx.y, b = blockIdx.z;

    const __half* base = qkv + (size_t)b * SEQ * (3 * D_MODEL) + h * HD;

    uint32_t qs_u = (uint32_t)__cvta_generic_to_shared(Qs);
    uint32_t ks_u = (uint32_t)__cvta_generic_to_shared(Ks0);
    const uint32_t* Qsw = (const uint32_t*)Qs;
    uint32_t* Psw = (uint32_t*)Ps;

    #pragma unroll
    for (int i = 0; i < 4; i++) {
        int idx = i * 256 + tid;
        int r = idx >> 3, c8 = (idx & 7) * 8;
        cp16(qs_u + (uint32_t)(r * TS_H + c8) * 2u,
             base + (size_t)(qb * QT + r) * (3 * D_MODEL) + c8);
    }
    asm volatile("cp.async.commit_group;\n" ::: "memory");

    float o[8][4];
    #pragma unroll
    for (int nt = 0; nt < 8; nt++)
        #pragma unroll
        for (int r = 0; r < 4; r++) o[nt][r] = 0.0f;
    float m0 = -INFINITY, m1 = -INFINITY, l0 = 0.0f, l1 = 0.0f;

    int qrow_lo = qb * QT + warp * 16;
    int mrow = warp * 16 + g;
    int pr0 = warp * 16 + g;
    int q0g = qb * QT + warp * 16 + g;
    int q1g = q0g + 8;

    int tp = tid & 31;
    int dgrp = tid >> 5;

    // one 64-key tile: S, mask, softmax, P store, o-rescale + PV
    auto do_tile = [&](int kt, const uint32_t* Ksw, const uint32_t* Vw, bool pv_ready) {
        bool active = (kt * 64 <= qrow_lo + 15);
        if (!active) return;

        float s[8][4];
        #pragma unroll
        for (int nt = 0; nt < 8; nt++)
            #pragma unroll
            for (int r = 0; r < 4; r++) s[nt][r] = 0.0f;

        #pragma unroll
        for (int ks = 0; ks < 4; ks++) {
            uint32_t a[4], bb[8][2];
            a[0] = Qsw[mrow * 36 + ks * 8 + tig];
            a[1] = Qsw[(mrow + 8) * 36 + ks * 8 + tig];
            a[2] = Qsw[mrow * 36 + ks * 8 + 4 + tig];
            a[3] = Qsw[(mrow + 8) * 36 + ks * 8 + 4 + tig];
            #pragma unroll
            for (int nt = 0; nt < 8; nt++) {
                bb[nt][0] = Ksw[(nt * 8 + g) * 36 + ks * 8 + tig];
                bb[nt][1] = Ksw[(nt * 8 + g) * 36 + ks * 8 + 4 + tig];
            }
            #pragma unroll
            for (int nt = 0; nt < 8; nt++) MMA_F16(s[nt], a, bb[nt]);
        }

        const float scale = 0.125f;
        bool diag = (kt * 64 + 63 > qrow_lo);
        #pragma unroll
        for (int nt = 0; nt < 8; nt++) {
            int key = kt * 64 + nt * 8 + 2 * tig;
            s[nt][0] *= scale; s[nt][1] *= scale;
            s[nt][2] *= scale; s[nt][3] *= scale;
            if (diag) {
                if (key     > q0g) s[nt][0] = -1e30f;
                if (key + 1 > q0g) s[nt][1] = -1e30f;
                if (key     > q1g) s[nt][2] = -1e30f;
                if (key + 1 > q1g) s[nt][3] = -1e30f;
            }
        }

        float rmax0 = -INFINITY, rmax1 = -INFINITY;
        #pragma unroll
        for (int nt = 0; nt < 8; nt++) {
            rmax0 = fmaxf(rmax0, fmaxf(s[nt][0], s[nt][1]));
            rmax1 = fmaxf(rmax1, fmaxf(s[nt][2], s[nt][3]));
        }
        rmax0 = fmaxf(rmax0, __shfl_xor_sync(0xffffffffu, rmax0, 1));
        rmax0 = fmaxf(rmax0, __shfl_xor_sync(0xffffffffu, rmax0, 2));
        rmax1 = fmaxf(rmax1, __shfl_xor_sync(0xffffffffu, rmax1, 1));
        rmax1 = fmaxf(rmax1, __shfl_xor_sync(0xffffffffu, rmax1, 2));

        float mn0 = fmaxf(m0, rmax0), mn1 = fmaxf(m1, rmax1);
        float corr0 = __expf(m0 - mn0), corr1 = __expf(m1 - mn1);

        float rs0 = 0.0f, rs1 = 0.0f;
        #pragma unroll
        for (int nt = 0; nt < 8; nt++) {
            s[nt][0] = __expf(s[nt][0] - mn0);
            s[nt][1] = __expf(s[nt][1] - mn0);
            s[nt][2] = __expf(s[nt][2] - mn1);
            s[nt][3] = __expf(s[nt][3] - mn1);
            rs0 += s[nt][0] + s[nt][1];
            rs1 += s[nt][2] + s[nt][3];
        }
        rs0 += __shfl_xor_sync(0xffffffffu, rs0, 1);
        rs0 += __shfl_xor_sync(0xffffffffu, rs0, 2);
        rs1 += __shfl_xor_sync(0xffffffffu, rs1, 1);
        rs1 += __shfl_xor_sync(0xffffffffu, rs1, 2);

        l0 = l0 * corr0 + rs0;  m0 = mn0;
        l1 = l1 * corr1 + rs1;  m1 = mn1;

        #pragma unroll
        for (int nt = 0; nt < 8; nt++) {
            __half2 p0 = __floats2half2_rn(s[nt][0], s[nt][1]);
            __half2 p1 = __floats2half2_rn(s[nt][2], s[nt][3]);
            Psw[pr0 * 36 + nt * 4 + tig]       = *(uint32_t*)&p0;
            Psw[(pr0 + 8) * 36 + nt * 4 + tig] = *(uint32_t*)&p1;
        }
        __syncwarp();          // P visible within warp before PV

        #pragma unroll
        for (int nt = 0; nt < 8; nt++) {
            o[nt][0] *= corr0; o[nt][1] *= corr0;
            o[nt][2] *= corr1; o[nt][3] *= corr1;
        }
        #pragma unroll
        for (int ks = 0; ks < 4; ks++) {
            uint32_t a[4], bb[8][2];
            a[0] = Psw[pr0 * 36 + ks * 8 + tig];
            a[1] = Psw[(pr0 + 8) * 36 + ks * 8 + tig];
            a[2] = Psw[pr0 * 36 + ks * 8 + 4 + tig];
            a[3] = Psw[(pr0 + 8) * 36 + ks * 8 + 4 + tig];
            #pragma unroll
            for (int nt = 0; nt < 8; nt++) {
                bb[nt][0] = Vw[(nt * 8 + g) * 36 + ks * 8 + tig];
                bb[nt][1] = Vw[(nt * 8 + g) * 36 + ks * 8 + 4 + tig];
            }
            #pragma unroll
            for (int nt = 0; nt < 8; nt++) MMA_F16(o[nt], a, bb[nt]);
        }
        (void)pv_ready;
    };

    int pairs = qb + 1;
    __half2 va[4], vb[4];

    for (int p = 0; p < pairs; p++) {
        int ktA = 2 * p, ktB = 2 * p + 1;
        __syncthreads();   // previous pair's Ks/Vt/Ps fully consumed

        // K pair cp.async (one group)
        #pragma unroll
        for (int i = 0; i < 4; i++) {
            int idx = i * 256 + tid;
            int r = idx >> 3, c8 = (idx & 7) * 8;   // r in 0..127 across both tiles
            cp16(ks_u + (uint32_t)(r * TS_H + c8) * 2u,
                 base + D_MODEL + (size_t)(ktA * KT + r) * (3 * D_MODEL) + c8);
        }
        asm volatile("cp.async.commit_group;\n" ::: "memory");

        // V(tile A) LDGs
        {
            const __half* v0r = base + 2 * D_MODEL + (size_t)(ktA * KT + 2 * tp) * (3 * D_MODEL);
            const __half* v1r = v0r + 3 * D_MODEL;
            #pragma unroll
            for (int j = 0; j < 4; j++) {
                int d = dgrp * 8 + 2 * j;
                va[j] = *(const __half2*)(v0r + d);
                vb[j] = *(const __half2*)(v1r + d);
            }
        }
        asm volatile("cp.async.wait_group 0;\n" ::: "memory");
        __syncthreads();   // K pair visible

        // repack V(A) -> frees va/vb
        {
            uint32_t* Vtw = (uint32_t*)(Vt0);
            #pragma unroll
            for (int j = 0; j < 4; j++) {
                int d = dgrp * 8 + 2 * j;
                __half2 lo = __lows2half2(va[j], vb[j]);
                __half2 hi = __highs2half2(va[j], vb[j]);
                Vtw[d * 36 + tp]       = *(uint32_t*)&lo;
                Vtw[(d + 1) * 36 + tp] = *(uint32_t*)&hi;
            }
        }
        // V(tile B) LDGs (latency hidden by S(A)+softmax below)
        {
            const __half* v0r = base + 2 * D_MODEL + (size_t)(ktB * KT + 2 * tp) * (3 * D_MODEL);
            const __half* v1r = v0r + 3 * D_MODEL;
            #pragma unroll
            for (int j = 0; j < 4; j++) {
                int d = dgrp * 8 + 2 * j;
                va[j] = *(const __half2*)(v0r + d);
                vb[j] = *(const __half2*)(v1r + d);
            }
        }

        // tile A compute up to (and incl.) softmax/P happens inside do_tile; but
        // PV(A) needs Vt(A) from ALL warps -> barrier must come before do_tile's PV.
        // So: run S/softmax part manually split? Simpler: repack B, barrier, then both tiles.
        // Repack V(B) now (consumes va/vb), then one barrier covers Vt A+B.
        {
            uint32_t* Vtw = (uint32_t*)(Vt0 + KT * TS_H);
            #pragma unroll
            for (int j = 0; j < 4; j++) {
                int d = dgrp * 8 + 2 * j;
                __half2 lo = __lows2half2(va[j], vb[j]);
                __half2 hi = __highs2half2(va[j], vb[j]);
                Vtw[d * 36 + tp]       = *(uint32_t*)&lo;
                Vtw[(d + 1) * 36 + tp] = *(uint32_t*)&hi;
            }
        }
        __syncthreads();   // Vt A+B complete block-wide

        do_tile(ktA, (const uint32_t*)(Ks0),              (const uint32_t*)(Vt0),              true);
        do_tile(ktB, (const uint32_t*)(Ks0 + KT * TS_H),  (const uint32_t*)(Vt0 + KT * TS_H),  true);
    }

    float il0 = 1.0f / l0, il1 = 1.0f / l1;
    size_t row0 = (size_t)(b * SEQ + qb * QT + warp * 16 + g);
    #pragma unroll
    for (int nt = 0; nt < 8; nt++) {
        int col = h * HD + nt * 8 + 2 * tig;
        *(__half2*)(out + row0 * D_MODEL + col) =
            __floats2half2_rn(o[nt][0] * il0, o[nt][1] * il0);
        *(__half2*)(out + (row0 + 8) * D_MODEL + col) =
            __floats2half2_rn(o[nt][2] * il1, o[nt][3] * il1);
    }
}

// ---------------- launch (multi-stream fork/join, graph-capturable) ----------------
extern "C" void kernel_launch(void* const* d_in, const int* in_sizes, int n_in,
                              void* d_out, int out_size)
{
    const float* x        = (const float*)d_in[0];
    const float* ln1_w    = (const float*)d_in[1];
    const float* ln1_b    = (const float*)d_in[2];
    const float* c_attn_w = (const float*)d_in[3];
    const float* c_attn_b = (const float*)d_in[4];
    const float* c_proj_w = (const float*)d_in[5];
    const float* c_proj_b = (const float*)d_in[6];
    const float* ln2_w    = (const float*)d_in[7];
    const float* ln2_b    = (const float*)d_in[8];
    const float* fc_w     = (const float*)d_in[9];
    const float* fc_b     = (const float*)d_in[10];
    const float* proj_w   = (const float*)d_in[11];
    const float* proj_b   = (const float*)d_in[12];
    float* out = (float*)d_out;

    float  *x1;
    __half *qkv, *ln1h, *attnh, *ln2h, *hh, *wattn, *wproj, *wfc, *wproj2;
    cudaGetSymbolAddress((void**)&x1,    g_x1);
    cudaGetSymbolAddress((void**)&qkv,   g_qkv);
    cudaGetSymbolAddress((void**)&ln1h,  g_ln1h);
    cudaGetSymbolAddress((void**)&attnh, g_attnh);
    cudaGetSymbolAddress((void**)&ln2h,  g_ln2h);
    cudaGetSymbolAddress((void**)&hh,    g_hh);
    cudaGetSymbolAddress((void**)&wattn, g_wattn);
    cudaGetSymbolAddress((void**)&wproj, g_wproj);
    cudaGetSymbolAddress((void**)&wfc,   g_wfc);
    cudaGetSymbolAddress((void**)&wproj2, g_wproj2);

    static cudaStream_t s_w = nullptr, s_l = nullptr;
    static cudaEvent_t ev_fork = nullptr, ev_w = nullptr, ev_ln = nullptr;
    static bool attr_done = false;
    if (!attr_done) {
        cudaFuncSetAttribute(gemm_fp16<0>, cudaFuncAttributeMaxDynamicSharedMemorySize, GEMM_SMEM_BYTES);
        cudaFuncSetAttribute(gemm_fp16<1>, cudaFuncAttributeMaxDynamicSharedMemorySize, GEMM_SMEM_BYTES);
        cudaFuncSetAttribute(gemm_fp16<2>, cudaFuncAttributeMaxDynamicSharedMemorySize, GEMM_SMEM_BYTES);
        cudaFuncSetAttribute(attn_tc,      cudaFuncAttributeMaxDynamicSharedMemorySize, ATTN_SMEM);
        cudaStreamCreateWithFlags(&s_w, cudaStreamNonBlocking);
        cudaStreamCreateWithFlags(&s_l, cudaStreamNonBlocking);
        cudaEventCreateWithFlags(&ev_fork, cudaEventDisableTiming);
        cudaEventCreateWithFlags(&ev_w,    cudaEventDisableTiming);
        cudaEventCreateWithFlags(&ev_ln,   cudaEventDisableTiming);
        attr_done = true;
    }

    // ---- fork ----
    cudaEventRecord(ev_fork, 0);
    cudaStreamWaitEvent(s_w, ev_fork, 0);
    cudaStreamWaitEvent(s_l, ev_fork, 0);

    ln_kernel<<<NTOK, 256, 0, s_l>>>(x, ln1_w, ln1_b, ln1h);
    cudaEventRecord(ev_ln, s_l);

    wconv<<<(D_MODEL / 2 * D_MODEL / 4 + 255) / 256, 256, 0, s_w>>>(c_proj_w, wproj, D_MODEL, D_MODEL);
    wconv<<<(D_MODEL / 2 * 4 * D_MODEL / 4 + 255) / 256, 256, 0, s_w>>>(fc_w, wfc, D_MODEL, 4 * D_MODEL);
    wconv<<<(4 * D_MODEL / 2 * D_MODEL / 4 + 255) / 256, 256, 0, s_w>>>(proj_w, wproj2, 4 * D_MODEL, D_MODEL);
    cudaEventRecord(ev_w, s_w);

    wconv<<<(D_MODEL / 2 * 3 * D_MODEL / 4 + 255) / 256, 256>>>(c_attn_w, wattn, D_MODEL, 3 * D_MODEL);
    cudaStreamWaitEvent(0, ev_ln, 0);
    gemm_fp16<0><<<dim3(3 * D_MODEL / BN, NTOK / BM), 256, GEMM_SMEM_BYTES>>>(
        ln1h, wattn, c_attn_b, nullptr, nullptr, qkv, NTOK, 3 * D_MODEL, D_MODEL);
    attn_tc<<<dim3(SEQ / QT, NHEAD, BATCH), 256, ATTN_SMEM>>>(qkv, attnh);

    cudaStreamWaitEvent(0, ev_w, 0);
    gemm_fp16<1><<<dim3(D_MODEL / BN, NTOK / BM), 256, GEMM_SMEM_BYTES>>>(
        attnh, wproj, c_proj_b, x, x1, nullptr, NTOK, D_MODEL, D_MODEL);
    ln_kernel<<<NTOK, 256>>>(x1, ln2_w, ln2_b, ln2h);
    gemm_fp16<2><<<dim3(4 * D_MODEL / BN, NTOK / BM), 256, GEMM_SMEM_BYTES>>>(
        ln2h, wfc, fc_b, nullptr, nullptr, hh, NTOK, 4 * D_MODEL, D_MODEL);
    gemm_fp16<1><<<dim3(D_MODEL / BN, NTOK / BM), 256, GEMM_SMEM_BYTES>>>(
        hh, wproj2, proj_b, x1, out, nullptr, NTOK, D_MODEL, 4 * D_MODEL);
}